// round 1
// baseline (speedup 1.0000x reference)
#include <cuda_runtime.h>
#include <math.h>

#define Bb  4
#define Ss  2048
#define Dd  1024
#define Hh  16
#define HDd 64
#define Mm  (Bb*Ss)   // 8192

// Scratch (device globals: allocation-free per harness rules)
__device__ float g_q[(size_t)Mm * Dd];
__device__ float g_k[(size_t)Mm * Dd];
__device__ float g_v[(size_t)Mm * Dd];
__device__ float g_ctx[(size_t)Mm * Dd];

// ---------------------------------------------------------------------------
// NT GEMM: C[M,N] = A[M,K] @ W[N,K]^T + bias[N]
// REMAP=1: scatter output to [B,H,S,HD] layout (for Q/K/V projections)
// BM=BN=128, BK=16, 256 threads, 8x8 per-thread tile.
// ---------------------------------------------------------------------------
template <int REMAP>
__global__ __launch_bounds__(256)
void gemm_nt(const float* __restrict__ A, const float* __restrict__ W,
             const float* __restrict__ bias, float* __restrict__ C,
             int M, int N, int K)
{
    const int BM = 128, BK = 16, PAD = 17;
    __shared__ float As[BM * PAD];
    __shared__ float Bs[BM * PAD];

    const int tid = threadIdx.x;
    const int tx = tid & 15;
    const int ty = tid >> 4;
    const int m0 = blockIdx.y * BM;
    const int n0 = blockIdx.x * BM;

    float acc[8][8];
#pragma unroll
    for (int i = 0; i < 8; i++)
#pragma unroll
        for (int j = 0; j < 8; j++) acc[i][j] = 0.f;

    for (int k0 = 0; k0 < K; k0 += BK) {
        // Load 128x16 tiles of A and W (both K-major -> coalesced float4)
#pragma unroll
        for (int it = 0; it < 2; it++) {
            int idx = tid + it * 256;      // 512 float4 per operand
            int r   = idx >> 2;            // row in tile
            int c4  = (idx & 3) * 4;       // k-offset
            float4 va = *(const float4*)(A + (size_t)(m0 + r) * K + k0 + c4);
            As[r * PAD + c4 + 0] = va.x;
            As[r * PAD + c4 + 1] = va.y;
            As[r * PAD + c4 + 2] = va.z;
            As[r * PAD + c4 + 3] = va.w;
            float4 vb = *(const float4*)(W + (size_t)(n0 + r) * K + k0 + c4);
            Bs[r * PAD + c4 + 0] = vb.x;
            Bs[r * PAD + c4 + 1] = vb.y;
            Bs[r * PAD + c4 + 2] = vb.z;
            Bs[r * PAD + c4 + 3] = vb.w;
        }
        __syncthreads();

#pragma unroll
        for (int k = 0; k < BK; k++) {
            float a[8], b[8];
#pragma unroll
            for (int i = 0; i < 8; i++) a[i] = As[(ty * 8 + i) * PAD + k];
#pragma unroll
            for (int j = 0; j < 8; j++) b[j] = Bs[(tx * 8 + j) * PAD + k];
#pragma unroll
            for (int i = 0; i < 8; i++)
#pragma unroll
                for (int j = 0; j < 8; j++) acc[i][j] += a[i] * b[j];
        }
        __syncthreads();
    }

    // Epilogue: bias + store (optionally remapped to [B,H,S,HD])
#pragma unroll
    for (int i = 0; i < 8; i++) {
        int m = m0 + ty * 8 + i;
#pragma unroll
        for (int j = 0; j < 8; j++) {
            int n = n0 + tx * 8 + j;
            float v = acc[i][j] + bias[n];
            if (REMAP) {
                int b  = m / Ss, s  = m % Ss;
                int h  = n / HDd, hd = n % HDd;
                C[(((size_t)b * Hh + h) * Ss + s) * HDd + hd] = v;
            } else {
                C[(size_t)m * N + n] = v;
            }
        }
    }
}

// ---------------------------------------------------------------------------
// Flash attention: one CTA per (64-row Q tile, head, batch).
// Natural-layout SMEM tiles (stride 65 to dodge bank conflicts).
// K tile SMEM is reused for the P tile.
// ---------------------------------------------------------------------------
#define BQ   64
#define BKV  64
#define APAD 65
#define ATTN_SMEM (3 * BQ * APAD * 4)

__global__ __launch_bounds__(256)
void attn_kernel(const float* __restrict__ q, const float* __restrict__ k,
                 const float* __restrict__ v, float* __restrict__ ctx)
{
    extern __shared__ float sm[];
    float* Qs  = sm;                 // [64][65] Q tile
    float* KPs = sm + BQ * APAD;     // [64][65] K tile, then P tile
    float* Vs  = sm + 2 * BQ * APAD; // [64][65] V tile

    const int tid = threadIdx.x;
    const int tx = tid & 15;
    const int ty = tid >> 4;
    const int q0 = blockIdx.x * BQ;
    const int h  = blockIdx.y;
    const int b  = blockIdx.z;
    const size_t base = ((size_t)b * Hh + h) * (size_t)Ss * HDd;

    // Load Q tile (natural [row][hd] layout)
#pragma unroll
    for (int it = 0; it < 4; it++) {
        int idx = tid + it * 256;      // 1024 float4
        int r   = idx >> 4;
        int c4  = (idx & 15) * 4;
        float4 vq = *(const float4*)(q + base + (size_t)(q0 + r) * HDd + c4);
        Qs[r * APAD + c4 + 0] = vq.x;
        Qs[r * APAD + c4 + 1] = vq.y;
        Qs[r * APAD + c4 + 2] = vq.z;
        Qs[r * APAD + c4 + 3] = vq.w;
    }

    float m_i[4], l_i[4], o[4][4];
#pragma unroll
    for (int i = 0; i < 4; i++) {
        m_i[i] = -INFINITY;
        l_i[i] = 0.f;
#pragma unroll
        for (int j = 0; j < 4; j++) o[i][j] = 0.f;
    }
    __syncthreads();

    const float scale = 0.125f; // 1/sqrt(64)

    for (int kv0 = 0; kv0 < Ss; kv0 += BKV) {
        // Load K tile and V tile
#pragma unroll
        for (int it = 0; it < 4; it++) {
            int idx = tid + it * 256;
            int r   = idx >> 4;
            int c4  = (idx & 15) * 4;
            float4 vk = *(const float4*)(k + base + (size_t)(kv0 + r) * HDd + c4);
            KPs[r * APAD + c4 + 0] = vk.x;
            KPs[r * APAD + c4 + 1] = vk.y;
            KPs[r * APAD + c4 + 2] = vk.z;
            KPs[r * APAD + c4 + 3] = vk.w;
            float4 vv = *(const float4*)(v + base + (size_t)(kv0 + r) * HDd + c4);
            Vs[r * APAD + c4 + 0] = vv.x;
            Vs[r * APAD + c4 + 1] = vv.y;
            Vs[r * APAD + c4 + 2] = vv.z;
            Vs[r * APAD + c4 + 3] = vv.w;
        }
        __syncthreads();

        // Scores: s[i][j] = (Q row ty*4+i) . (K row tx*4+j)
        float s[4][4];
#pragma unroll
        for (int i = 0; i < 4; i++)
#pragma unroll
            for (int j = 0; j < 4; j++) s[i][j] = 0.f;

#pragma unroll 4
        for (int d = 0; d < HDd; d++) {
            float a[4], bb[4];
#pragma unroll
            for (int i = 0; i < 4; i++) a[i]  = Qs[(ty * 4 + i) * APAD + d];
#pragma unroll
            for (int j = 0; j < 4; j++) bb[j] = KPs[(tx * 4 + j) * APAD + d];
#pragma unroll
            for (int i = 0; i < 4; i++)
#pragma unroll
                for (int j = 0; j < 4; j++) s[i][j] += a[i] * bb[j];
        }

        // Online softmax per row (rows split across the 16-lane tx group)
        float alpha[4];
#pragma unroll
        for (int i = 0; i < 4; i++) {
            float mx = s[i][0] * scale;
#pragma unroll
            for (int j = 1; j < 4; j++) mx = fmaxf(mx, s[i][j] * scale);
#pragma unroll
            for (int off = 1; off < 16; off <<= 1)
                mx = fmaxf(mx, __shfl_xor_sync(0xffffffffu, mx, off));
            float mnew = fmaxf(m_i[i], mx);
            alpha[i] = __expf(m_i[i] - mnew);
            float rowsum = 0.f;
#pragma unroll
            for (int j = 0; j < 4; j++) {
                s[i][j] = __expf(s[i][j] * scale - mnew);
                rowsum += s[i][j];
            }
#pragma unroll
            for (int off = 1; off < 16; off <<= 1)
                rowsum += __shfl_xor_sync(0xffffffffu, rowsum, off);
            l_i[i] = l_i[i] * alpha[i] + rowsum;
            m_i[i] = mnew;
        }

        __syncthreads(); // everyone done reading K tile
        // Write P over the K tile: natural [q_row][kv_col]
#pragma unroll
        for (int i = 0; i < 4; i++)
#pragma unroll
            for (int j = 0; j < 4; j++)
                KPs[(ty * 4 + i) * APAD + tx * 4 + j] = s[i][j];
        __syncthreads();

        // Rescale accumulator
#pragma unroll
        for (int i = 0; i < 4; i++)
#pragma unroll
            for (int j = 0; j < 4; j++) o[i][j] *= alpha[i];

        // O += P @ V
#pragma unroll 4
        for (int jj = 0; jj < BKV; jj++) {
            float p[4], vv[4];
#pragma unroll
            for (int i = 0; i < 4; i++) p[i]  = KPs[(ty * 4 + i) * APAD + jj];
#pragma unroll
            for (int j = 0; j < 4; j++) vv[j] = Vs[jj * APAD + tx * 4 + j];
#pragma unroll
            for (int i = 0; i < 4; i++)
#pragma unroll
                for (int j = 0; j < 4; j++) o[i][j] += p[i] * vv[j];
        }
        __syncthreads(); // before next tile overwrites K/V
    }

    // Finalize and write ctx in [B,S,D] layout
#pragma unroll
    for (int i = 0; i < 4; i++) {
        float inv = 1.f / l_i[i];
        int srow = q0 + ty * 4 + i;
#pragma unroll
        for (int j = 0; j < 4; j++) {
            ctx[((size_t)b * Ss + srow) * Dd + h * HDd + tx * 4 + j] = o[i][j] * inv;
        }
    }
}

// ---------------------------------------------------------------------------
extern "C" void kernel_launch(void* const* d_in, const int* in_sizes, int n_in,
                              void* d_out, int out_size)
{
    const float* x  = (const float*)d_in[0];
    const float* Wq = (const float*)d_in[1];
    const float* bq = (const float*)d_in[2];
    const float* Wk = (const float*)d_in[3];
    const float* bk = (const float*)d_in[4];
    const float* Wv = (const float*)d_in[5];
    const float* bv = (const float*)d_in[6];
    const float* Wo = (const float*)d_in[7];
    const float* bo = (const float*)d_in[8];
    float* out = (float*)d_out;

    float *q, *k, *v, *ctx;
    cudaGetSymbolAddress((void**)&q,   g_q);
    cudaGetSymbolAddress((void**)&k,   g_k);
    cudaGetSymbolAddress((void**)&v,   g_v);
    cudaGetSymbolAddress((void**)&ctx, g_ctx);

    cudaFuncSetAttribute(attn_kernel,
                         cudaFuncAttributeMaxDynamicSharedMemorySize, ATTN_SMEM);

    dim3 gg(Dd / 128, Mm / 128);   // (8, 64)
    gemm_nt<1><<<gg, 256>>>(x, Wq, bq, q, Mm, Dd, Dd);
    gemm_nt<1><<<gg, 256>>>(x, Wk, bk, k, Mm, Dd, Dd);
    gemm_nt<1><<<gg, 256>>>(x, Wv, bv, v, Mm, Dd, Dd);

    dim3 ga(Ss / BQ, Hh, Bb);      // (32, 16, 4)
    attn_kernel<<<ga, 256, ATTN_SMEM>>>(q, k, v, ctx);

    gemm_nt<0><<<gg, 256>>>(ctx, Wo, bo, out, Mm, Dd, Dd);
}

// round 3
// speedup vs baseline: 1.8465x; 1.8465x over previous
#include <cuda_runtime.h>
#include <cuda_bf16.h>
#include <math.h>
#include <stdint.h>

#define Bb  4
#define Ss  2048
#define Dd  1024
#define Hh  16
#define HDd 64
#define Mm  (Bb*Ss)   // 8192

// ---------------------------------------------------------------------------
// Scratch (device globals: allocation-free per harness rules)
// ---------------------------------------------------------------------------
__device__ float g_q[(size_t)Mm * Dd];
__device__ float g_k[(size_t)Mm * Dd];
__device__ float g_v[(size_t)Mm * Dd];
__device__ __nv_bfloat16 g_xh[(size_t)Mm * Dd];
__device__ __nv_bfloat16 g_xl[(size_t)Mm * Dd];
__device__ __nv_bfloat16 g_wh[(size_t)4 * Dd * Dd];
__device__ __nv_bfloat16 g_wl[(size_t)4 * Dd * Dd];
__device__ __nv_bfloat16 g_ch[(size_t)Mm * Dd];
__device__ __nv_bfloat16 g_cl[(size_t)Mm * Dd];

// ---------------------------------------------------------------------------
// Helpers
// ---------------------------------------------------------------------------
__device__ __forceinline__ uint32_t smem_u32(const void* p) {
    uint32_t a;
    asm("{ .reg .u64 t; cvta.to.shared.u64 t, %1; cvt.u32.u64 %0, t; }"
        : "=r"(a) : "l"(p));
    return a;
}

__device__ __forceinline__ void split4(float4 v, uint2& hi, uint2& lo) {
    __nv_bfloat16 h0 = __float2bfloat16(v.x);
    __nv_bfloat16 h1 = __float2bfloat16(v.y);
    __nv_bfloat16 h2 = __float2bfloat16(v.z);
    __nv_bfloat16 h3 = __float2bfloat16(v.w);
    __nv_bfloat16 l0 = __float2bfloat16(v.x - __bfloat162float(h0));
    __nv_bfloat16 l1 = __float2bfloat16(v.y - __bfloat162float(h1));
    __nv_bfloat16 l2 = __float2bfloat16(v.z - __bfloat162float(h2));
    __nv_bfloat16 l3 = __float2bfloat16(v.w - __bfloat162float(h3));
    hi.x = (uint32_t)__bfloat16_as_ushort(h0) | ((uint32_t)__bfloat16_as_ushort(h1) << 16);
    hi.y = (uint32_t)__bfloat16_as_ushort(h2) | ((uint32_t)__bfloat16_as_ushort(h3) << 16);
    lo.x = (uint32_t)__bfloat16_as_ushort(l0) | ((uint32_t)__bfloat16_as_ushort(l1) << 16);
    lo.y = (uint32_t)__bfloat16_as_ushort(l2) | ((uint32_t)__bfloat16_as_ushort(l3) << 16);
}

__device__ __forceinline__ void ldsm_x4(uint32_t addr, uint32_t* r) {
    asm volatile("ldmatrix.sync.aligned.m8n8.x4.shared.b16 {%0,%1,%2,%3}, [%4];"
        : "=r"(r[0]), "=r"(r[1]), "=r"(r[2]), "=r"(r[3]) : "r"(addr));
}

__device__ __forceinline__ void mma16816(float* c, const uint32_t* a, const uint32_t* b) {
    asm volatile(
        "mma.sync.aligned.m16n8k16.row.col.f32.bf16.bf16.f32 "
        "{%0,%1,%2,%3}, {%4,%5,%6,%7}, {%8,%9}, {%0,%1,%2,%3};"
        : "+f"(c[0]), "+f"(c[1]), "+f"(c[2]), "+f"(c[3])
        : "r"(a[0]), "r"(a[1]), "r"(a[2]), "r"(a[3]), "r"(b[0]), "r"(b[1]));
}

__device__ __forceinline__ void cp16(uint32_t dst, const void* src) {
    asm volatile("cp.async.cg.shared.global [%0], [%1], 16;" :: "r"(dst), "l"(src));
}
#define CP_COMMIT() asm volatile("cp.async.commit_group;" ::: "memory")
#define CP_WAIT1()  asm volatile("cp.async.wait_group 1;" ::: "memory")
#define CP_WAIT0()  asm volatile("cp.async.wait_group 0;" ::: "memory")

// ---------------------------------------------------------------------------
// fp32 -> bf16 hi/lo split (elementwise, bandwidth-bound)
// ---------------------------------------------------------------------------
__global__ __launch_bounds__(256)
void split_kernel(const float4* __restrict__ in, uint2* __restrict__ hi,
                  uint2* __restrict__ lo, int n4)
{
    int i = blockIdx.x * blockDim.x + threadIdx.x;
    if (i < n4) {
        uint2 h, l;
        split4(in[i], h, l);
        hi[i] = h;
        lo[i] = l;
    }
}

// ---------------------------------------------------------------------------
// HMMA GEMM (compensated bf16): C[M,N] = A[M,K] @ W[N,K]^T + bias[N]
// 128x128 CTA tile, 512 threads, 16 warps of 32x32, KC=32, 2-stage cp.async.
// SMEM tiles: 128 rows x 32 bf16, padded to 80B rows (conflict-free ldmatrix).
// REMAP=1: scatter output to [B,H,S,HD].
// ---------------------------------------------------------------------------
#define GKC 32
#define NCH (Dd / GKC)          // 32
#define MAT_BYTES (128 * 80)    // 10240
#define STAGE (4 * MAT_BYTES)   // 40960
#define GSMEM (2 * STAGE)       // 81920

__device__ __forceinline__ void gemm_issue(
    uint32_t st, int tid, int m0, int n0, int k0,
    const __nv_bfloat16* __restrict__ Ah, const __nv_bfloat16* __restrict__ Al,
    const __nv_bfloat16* __restrict__ Bh, const __nv_bfloat16* __restrict__ Bl)
{
    const int r  = tid >> 2;          // 0..127
    const int c8 = (tid & 3) * 8;     // 0,8,16,24 (bf16 units)
    const size_t offA = (size_t)(m0 + r) * Dd + k0 + c8;
    const size_t offB = (size_t)(n0 + r) * Dd + k0 + c8;
    const uint32_t d = st + r * 80 + c8 * 2;
    cp16(d,                 Ah + offA);
    cp16(d + MAT_BYTES,     Al + offA);
    cp16(d + 2 * MAT_BYTES, Bh + offB);
    cp16(d + 3 * MAT_BYTES, Bl + offB);
    CP_COMMIT();
}

template <int REMAP>
__global__ __launch_bounds__(512)
void gemm_tc(const __nv_bfloat16* __restrict__ Ah, const __nv_bfloat16* __restrict__ Al,
             const __nv_bfloat16* __restrict__ Bh, const __nv_bfloat16* __restrict__ Bl,
             const float* __restrict__ bias, float* __restrict__ C)
{
    extern __shared__ char sm[];
    const uint32_t sbase = smem_u32(sm);

    const int tid  = threadIdx.x;
    const int wid  = tid >> 5;
    const int lane = tid & 31;
    const int m0 = blockIdx.y * 128;
    const int n0 = blockIdx.x * 128;
    const int wm = (wid & 3) * 32;     // warp m offset in tile
    const int wn = (wid >> 2) * 32;    // warp n offset in tile

    float acc[2][4][4];
#pragma unroll
    for (int mt = 0; mt < 2; mt++)
#pragma unroll
        for (int nt = 0; nt < 4; nt++)
#pragma unroll
            for (int i = 0; i < 4; i++) acc[mt][nt][i] = 0.f;

    // ldmatrix lane addressing
    const int a_r = lane & 15;             // row 0..15 within 16x16 a tile
    const int a_k = (lane >> 4) * 8;       // k offset 0/8
    const int b_r = (lane & 7) + ((lane >> 4) << 3);  // n row: +8 for lanes>=16
    const int b_k = (lane & 8) ? 8 : 0;    // k offset 0/8

    gemm_issue(sbase, tid, m0, n0, 0, Ah, Al, Bh, Bl);

    for (int c = 0; c < NCH; c++) {
        const int s = c & 1;
        if (c + 1 < NCH) {
            gemm_issue(sbase + (s ^ 1) * STAGE, tid, m0, n0, (c + 1) * GKC,
                       Ah, Al, Bh, Bl);
            CP_WAIT1();
        } else {
            CP_WAIT0();
        }
        __syncthreads();

        const uint32_t st = sbase + s * STAGE;
#pragma unroll
        for (int ks = 0; ks < 2; ks++) {
            uint32_t af[2][4], alf[2][4], bf[2][4], blf[2][4];
#pragma unroll
            for (int mt = 0; mt < 2; mt++) {
                uint32_t addr = st + (wm + mt * 16 + a_r) * 80 + (ks * 16 + a_k) * 2;
                ldsm_x4(addr, af[mt]);
                ldsm_x4(addr + MAT_BYTES, alf[mt]);
            }
#pragma unroll
            for (int nq = 0; nq < 2; nq++) {
                uint32_t addr = st + 2 * MAT_BYTES
                              + (wn + nq * 16 + b_r) * 80 + (ks * 16 + b_k) * 2;
                ldsm_x4(addr, bf[nq]);
                ldsm_x4(addr + MAT_BYTES, blf[nq]);
            }
#pragma unroll
            for (int mt = 0; mt < 2; mt++)
#pragma unroll
                for (int nt = 0; nt < 4; nt++) {
                    const uint32_t* bh = &bf[nt >> 1][(nt & 1) * 2];
                    const uint32_t* bl = &blf[nt >> 1][(nt & 1) * 2];
                    mma16816(acc[mt][nt], af[mt], bh);   // Ah*Bh
                    mma16816(acc[mt][nt], alf[mt], bh);  // Al*Bh
                    mma16816(acc[mt][nt], af[mt], bl);   // Ah*Bl
                }
        }
        __syncthreads();
    }

    // Epilogue: c-frag thread t holds rows (t/4, t/4+8), cols (t%4)*2 + {0,1}
    const int tg = lane >> 2;
    const int tc = (lane & 3) * 2;
#pragma unroll
    for (int mt = 0; mt < 2; mt++) {
#pragma unroll
        for (int nt = 0; nt < 4; nt++) {
            const int n = n0 + wn + nt * 8 + tc;
            const float b0 = bias[n], b1 = bias[n + 1];
#pragma unroll
            for (int half = 0; half < 2; half++) {
                const int m = m0 + wm + mt * 16 + tg + half * 8;
                float2 ov;
                ov.x = acc[mt][nt][half * 2 + 0] + b0;
                ov.y = acc[mt][nt][half * 2 + 1] + b1;
                if (REMAP) {
                    const int bi = m >> 11, sr = m & 2047;
                    const int h = n >> 6, hd = n & 63;
                    *(float2*)(C + (((size_t)bi * Hh + h) * Ss + sr) * HDd + hd) = ov;
                } else {
                    *(float2*)(C + (size_t)m * Dd + n) = ov;
                }
            }
        }
    }
}

// ---------------------------------------------------------------------------
// Flash attention: BQ=128 q rows, BKV=64 per tile, 256 threads,
// 8(q)x4(kv/hd) per-thread tile, transposed smem -> broadcast/CF LDS.128.
// Writes ctx directly as bf16 hi/lo for the output GEMM.
// ---------------------------------------------------------------------------
#define BQ    128
#define BKV   64
#define QSTR  132
#define KSTR  68
#define VSTR  68
#define PSTR  132
#define ATTN_SMEM ((64*QSTR + 64*KSTR + 64*VSTR + 64*PSTR) * 4)

__global__ __launch_bounds__(256)
void attn_kernel(const float* __restrict__ q, const float* __restrict__ k,
                 const float* __restrict__ v,
                 __nv_bfloat16* __restrict__ ch, __nv_bfloat16* __restrict__ cl)
{
    extern __shared__ float smf[];
    float* Qt = smf;                        // [d][q]    64x132
    float* Kt = Qt + 64 * QSTR;             // [d][kv]   64x68
    float* Vs = Kt + 64 * KSTR;             // [kv][hd]  64x68
    float* Pt = Vs + 64 * VSTR;             // [kv][q]   64x132

    const int tid = threadIdx.x;
    const int tx = tid & 15;
    const int ty = tid >> 4;
    const int q0 = blockIdx.x * BQ;
    const int h  = blockIdx.y;
    const int b  = blockIdx.z;
    const size_t base = ((size_t)b * Hh + h) * (size_t)Ss * HDd;
    const float scale = 0.125f;

#pragma unroll
    for (int it = 0; it < 8; it++) {
        int idx = tid + it * 256;
        int r = idx >> 4, c4 = (idx & 15) * 4;
        float4 vq = *(const float4*)(q + base + (size_t)(q0 + r) * HDd + c4);
        Qt[(c4 + 0) * QSTR + r] = vq.x * scale;
        Qt[(c4 + 1) * QSTR + r] = vq.y * scale;
        Qt[(c4 + 2) * QSTR + r] = vq.z * scale;
        Qt[(c4 + 3) * QSTR + r] = vq.w * scale;
    }

    float m_i[8], l_i[8], o[8][4];
#pragma unroll
    for (int i = 0; i < 8; i++) {
        m_i[i] = -INFINITY; l_i[i] = 0.f;
#pragma unroll
        for (int j = 0; j < 4; j++) o[i][j] = 0.f;
    }
    __syncthreads();

    for (int kv0 = 0; kv0 < Ss; kv0 += BKV) {
#pragma unroll
        for (int it = 0; it < 4; it++) {
            int idx = tid + it * 256;
            int r = idx >> 4, c4 = (idx & 15) * 4;
            float4 vk = *(const float4*)(k + base + (size_t)(kv0 + r) * HDd + c4);
            Kt[(c4 + 0) * KSTR + r] = vk.x;
            Kt[(c4 + 1) * KSTR + r] = vk.y;
            Kt[(c4 + 2) * KSTR + r] = vk.z;
            Kt[(c4 + 3) * KSTR + r] = vk.w;
            float4 vv = *(const float4*)(v + base + (size_t)(kv0 + r) * HDd + c4);
            *(float4*)(Vs + r * VSTR + c4) = vv;
        }
        __syncthreads();

        float s[8][4];
#pragma unroll
        for (int i = 0; i < 8; i++)
#pragma unroll
            for (int j = 0; j < 4; j++) s[i][j] = 0.f;

#pragma unroll 4
        for (int d = 0; d < HDd; d++) {
            float4 a0 = *(const float4*)(Qt + d * QSTR + ty * 8);
            float4 a1 = *(const float4*)(Qt + d * QSTR + ty * 8 + 4);
            float4 bk = *(const float4*)(Kt + d * KSTR + tx * 4);
            float a[8] = {a0.x, a0.y, a0.z, a0.w, a1.x, a1.y, a1.z, a1.w};
            float bv[4] = {bk.x, bk.y, bk.z, bk.w};
#pragma unroll
            for (int i = 0; i < 8; i++)
#pragma unroll
                for (int j = 0; j < 4; j++) s[i][j] += a[i] * bv[j];
        }

        float alpha[8];
#pragma unroll
        for (int i = 0; i < 8; i++) {
            float mx = fmaxf(fmaxf(s[i][0], s[i][1]), fmaxf(s[i][2], s[i][3]));
#pragma unroll
            for (int off = 1; off < 16; off <<= 1)
                mx = fmaxf(mx, __shfl_xor_sync(0xffffffffu, mx, off));
            float mnew = fmaxf(m_i[i], mx);
            alpha[i] = __expf(m_i[i] - mnew);
            float rs = 0.f;
#pragma unroll
            for (int j = 0; j < 4; j++) {
                s[i][j] = __expf(s[i][j] - mnew);
                rs += s[i][j];
            }
#pragma unroll
            for (int off = 1; off < 16; off <<= 1)
                rs += __shfl_xor_sync(0xffffffffu, rs, off);
            l_i[i] = l_i[i] * alpha[i] + rs;
            m_i[i] = mnew;
        }

#pragma unroll
        for (int j = 0; j < 4; j++) {
            *(float4*)(Pt + (tx * 4 + j) * PSTR + ty * 8) =
                make_float4(s[0][j], s[1][j], s[2][j], s[3][j]);
            *(float4*)(Pt + (tx * 4 + j) * PSTR + ty * 8 + 4) =
                make_float4(s[4][j], s[5][j], s[6][j], s[7][j]);
        }
#pragma unroll
        for (int i = 0; i < 8; i++)
#pragma unroll
            for (int j = 0; j < 4; j++) o[i][j] *= alpha[i];
        __syncthreads();

#pragma unroll 2
        for (int jj = 0; jj < BKV; jj++) {
            float4 p0 = *(const float4*)(Pt + jj * PSTR + ty * 8);
            float4 p1 = *(const float4*)(Pt + jj * PSTR + ty * 8 + 4);
            float4 vv = *(const float4*)(Vs + jj * VSTR + tx * 4);
            float p[8] = {p0.x, p0.y, p0.z, p0.w, p1.x, p1.y, p1.z, p1.w};
            float w[4] = {vv.x, vv.y, vv.z, vv.w};
#pragma unroll
            for (int i = 0; i < 8; i++)
#pragma unroll
                for (int j = 0; j < 4; j++) o[i][j] += p[i] * w[j];
        }
        __syncthreads();
    }

    // Finalize: write bf16 hi/lo ctx[b][s][h*64 + hd]
#pragma unroll
    for (int i = 0; i < 8; i++) {
        float inv = 1.f / l_i[i];
        int srow = q0 + ty * 8 + i;
        float4 ov = make_float4(o[i][0] * inv, o[i][1] * inv,
                                o[i][2] * inv, o[i][3] * inv);
        uint2 hi, lo;
        split4(ov, hi, lo);
        size_t idx = ((size_t)b * Ss + srow) * Dd + h * HDd + tx * 4;
        *(uint2*)(ch + idx) = hi;
        *(uint2*)(cl + idx) = lo;
    }
}

// ---------------------------------------------------------------------------
extern "C" void kernel_launch(void* const* d_in, const int* in_sizes, int n_in,
                              void* d_out, int out_size)
{
    const float* x  = (const float*)d_in[0];
    const float* Wq = (const float*)d_in[1];
    const float* bq = (const float*)d_in[2];
    const float* Wk = (const float*)d_in[3];
    const float* bk = (const float*)d_in[4];
    const float* Wv = (const float*)d_in[5];
    const float* bv = (const float*)d_in[6];
    const float* Wo = (const float*)d_in[7];
    const float* bo = (const float*)d_in[8];
    float* out = (float*)d_out;

    float *q, *k, *v;
    __nv_bfloat16 *xh, *xl, *wh, *wl, *ch, *cl;
    cudaGetSymbolAddress((void**)&q,  g_q);
    cudaGetSymbolAddress((void**)&k,  g_k);
    cudaGetSymbolAddress((void**)&v,  g_v);
    cudaGetSymbolAddress((void**)&xh, g_xh);
    cudaGetSymbolAddress((void**)&xl, g_xl);
    cudaGetSymbolAddress((void**)&wh, g_wh);
    cudaGetSymbolAddress((void**)&wl, g_wl);
    cudaGetSymbolAddress((void**)&ch, g_ch);
    cudaGetSymbolAddress((void**)&cl, g_cl);

    cudaFuncSetAttribute((const void*)gemm_tc<1>,
                         cudaFuncAttributeMaxDynamicSharedMemorySize, GSMEM);
    cudaFuncSetAttribute((const void*)gemm_tc<0>,
                         cudaFuncAttributeMaxDynamicSharedMemorySize, GSMEM);
    cudaFuncSetAttribute(attn_kernel,
                         cudaFuncAttributeMaxDynamicSharedMemorySize, ATTN_SMEM);

    // Split fp32 -> bf16 hi/lo
    const int nx4 = (Mm * Dd) / 4;   // x: 2M float4
    const int nw4 = (Dd * Dd) / 4;   // each W: 256K float4
    split_kernel<<<nx4 / 256, 256>>>((const float4*)x, (uint2*)xh, (uint2*)xl, nx4);
    const float* Ws[4] = {Wq, Wk, Wv, Wo};
    for (int i = 0; i < 4; i++)
        split_kernel<<<nw4 / 256, 256>>>((const float4*)Ws[i],
                                         (uint2*)(wh + (size_t)i * Dd * Dd),
                                         (uint2*)(wl + (size_t)i * Dd * Dd), nw4);

    dim3 gg(Dd / 128, Mm / 128);   // (8, 64)
    gemm_tc<1><<<gg, 512, GSMEM>>>(xh, xl, wh + 0 * (size_t)Dd * Dd, wl + 0 * (size_t)Dd * Dd, bq, q);
    gemm_tc<1><<<gg, 512, GSMEM>>>(xh, xl, wh + 1 * (size_t)Dd * Dd, wl + 1 * (size_t)Dd * Dd, bk, k);
    gemm_tc<1><<<gg, 512, GSMEM>>>(xh, xl, wh + 2 * (size_t)Dd * Dd, wl + 2 * (size_t)Dd * Dd, bv, v);

    dim3 ga(Ss / BQ, Hh, Bb);      // (16, 16, 4)
    attn_kernel<<<ga, 256, ATTN_SMEM>>>(q, k, v, ch, cl);

    gemm_tc<0><<<gg, 512, GSMEM>>>(ch, cl, wh + 3 * (size_t)Dd * Dd, wl + 3 * (size_t)Dd * Dd, bo, out);
}

// round 5
// speedup vs baseline: 4.0268x; 2.1808x over previous
#include <cuda_runtime.h>
#include <cuda_bf16.h>
#include <cuda_fp16.h>
#include <math.h>
#include <stdint.h>

#define Bb  4
#define Ss  2048
#define Dd  1024
#define Hh  16
#define HDd 64
#define Mm  (Bb*Ss)   // 8192

// ---------------------------------------------------------------------------
// Scratch (device globals: allocation-free per harness rules)
// ---------------------------------------------------------------------------
__device__ __nv_bfloat16 g_xh[(size_t)Mm * Dd];
__device__ __nv_bfloat16 g_xl[(size_t)Mm * Dd];
__device__ __nv_bfloat16 g_wh[(size_t)4 * Dd * Dd];
__device__ __nv_bfloat16 g_wl[(size_t)4 * Dd * Dd];
__device__ __nv_bfloat16 g_qh[(size_t)Mm * Dd];
__device__ __nv_bfloat16 g_ql[(size_t)Mm * Dd];
__device__ __nv_bfloat16 g_kh[(size_t)Mm * Dd];
__device__ __nv_bfloat16 g_kl[(size_t)Mm * Dd];
__device__ __half        g_vt[(size_t)Mm * Dd];
__device__ __nv_bfloat16 g_ch[(size_t)Mm * Dd];
__device__ __nv_bfloat16 g_cl[(size_t)Mm * Dd];

// 0.125 * log2(e)  (folded into Q so softmax runs in exp2 domain)
#define QSCALE 0.18033688011112042f

// ---------------------------------------------------------------------------
// Helpers
// ---------------------------------------------------------------------------
__device__ __forceinline__ uint32_t smem_u32(const void* p) {
    uint32_t a;
    asm("{ .reg .u64 t; cvta.to.shared.u64 t, %1; cvt.u32.u64 %0, t; }"
        : "=r"(a) : "l"(p));
    return a;
}

__device__ __forceinline__ float ex2(float x) {
    float y;
    asm("ex2.approx.ftz.f32 %0, %1;" : "=f"(y) : "f"(x));
    return y;
}

__device__ __forceinline__ void split4(float4 v, uint2& hi, uint2& lo) {
    __nv_bfloat16 h0 = __float2bfloat16(v.x);
    __nv_bfloat16 h1 = __float2bfloat16(v.y);
    __nv_bfloat16 h2 = __float2bfloat16(v.z);
    __nv_bfloat16 h3 = __float2bfloat16(v.w);
    __nv_bfloat16 l0 = __float2bfloat16(v.x - __bfloat162float(h0));
    __nv_bfloat16 l1 = __float2bfloat16(v.y - __bfloat162float(h1));
    __nv_bfloat16 l2 = __float2bfloat16(v.z - __bfloat162float(h2));
    __nv_bfloat16 l3 = __float2bfloat16(v.w - __bfloat162float(h3));
    hi.x = (uint32_t)__bfloat16_as_ushort(h0) | ((uint32_t)__bfloat16_as_ushort(h1) << 16);
    hi.y = (uint32_t)__bfloat16_as_ushort(h2) | ((uint32_t)__bfloat16_as_ushort(h3) << 16);
    lo.x = (uint32_t)__bfloat16_as_ushort(l0) | ((uint32_t)__bfloat16_as_ushort(l1) << 16);
    lo.y = (uint32_t)__bfloat16_as_ushort(l2) | ((uint32_t)__bfloat16_as_ushort(l3) << 16);
}

__device__ __forceinline__ void ldsm_x4(uint32_t addr, uint32_t* r) {
    asm volatile("ldmatrix.sync.aligned.m8n8.x4.shared.b16 {%0,%1,%2,%3}, [%4];"
        : "=r"(r[0]), "=r"(r[1]), "=r"(r[2]), "=r"(r[3]) : "r"(addr));
}

__device__ __forceinline__ void mma16816(float* c, const uint32_t* a, const uint32_t* b) {
    asm volatile(
        "mma.sync.aligned.m16n8k16.row.col.f32.bf16.bf16.f32 "
        "{%0,%1,%2,%3}, {%4,%5,%6,%7}, {%8,%9}, {%0,%1,%2,%3};"
        : "+f"(c[0]), "+f"(c[1]), "+f"(c[2]), "+f"(c[3])
        : "r"(a[0]), "r"(a[1]), "r"(a[2]), "r"(a[3]), "r"(b[0]), "r"(b[1]));
}

__device__ __forceinline__ void mma16816h(float* c, const uint32_t* a, const uint32_t* b) {
    asm volatile(
        "mma.sync.aligned.m16n8k16.row.col.f32.f16.f16.f32 "
        "{%0,%1,%2,%3}, {%4,%5,%6,%7}, {%8,%9}, {%0,%1,%2,%3};"
        : "+f"(c[0]), "+f"(c[1]), "+f"(c[2]), "+f"(c[3])
        : "r"(a[0]), "r"(a[1]), "r"(a[2]), "r"(a[3]), "r"(b[0]), "r"(b[1]));
}

__device__ __forceinline__ uint32_t pack_h2(float a, float b) {
    __half2 h = __floats2half2_rn(a, b);
    return *(uint32_t*)&h;
}

__device__ __forceinline__ void cp16(uint32_t dst, const void* src) {
    asm volatile("cp.async.cg.shared.global [%0], [%1], 16;" :: "r"(dst), "l"(src));
}
#define CP_COMMIT() asm volatile("cp.async.commit_group;" ::: "memory")
#define CP_WAIT1()  asm volatile("cp.async.wait_group 1;" ::: "memory")
#define CP_WAIT0()  asm volatile("cp.async.wait_group 0;" ::: "memory")

// ---------------------------------------------------------------------------
// fp32 -> bf16 hi/lo split (elementwise, bandwidth-bound)
// ---------------------------------------------------------------------------
__global__ __launch_bounds__(256)
void split_kernel(const float4* __restrict__ in, uint2* __restrict__ hi,
                  uint2* __restrict__ lo, int n4)
{
    int i = blockIdx.x * blockDim.x + threadIdx.x;
    if (i < n4) {
        uint2 h, l;
        split4(in[i], h, l);
        hi[i] = h;
        lo[i] = l;
    }
}

// ---------------------------------------------------------------------------
// HMMA GEMM (compensated bf16): C[M,N] = A[M,K] @ W[N,K]^T + bias[N]
// 128x128 CTA tile, 512 threads, KC=32, 2-stage cp.async.
// MODE 0: fp32 [M,N] out.
// MODE 1: Q out — scaled by QSCALE, bf16 hi/lo, remap to [B,H,S,HD].
// MODE 2: K out — bf16 hi/lo, remap to [B,H,S,HD].
// MODE 3: V out — fp16, remap TRANSPOSED to [B,H,HD,S].
// ---------------------------------------------------------------------------
#define GKC 32
#define NCH (Dd / GKC)          // 32
#define MAT_BYTES (128 * 80)    // 10240
#define STAGE (4 * MAT_BYTES)   // 40960
#define GSMEM (2 * STAGE)       // 81920

__device__ __forceinline__ void gemm_issue(
    uint32_t st, int tid, int m0, int n0, int k0,
    const __nv_bfloat16* __restrict__ Ah, const __nv_bfloat16* __restrict__ Al,
    const __nv_bfloat16* __restrict__ Bh, const __nv_bfloat16* __restrict__ Bl)
{
    const int r  = tid >> 2;
    const int c8 = (tid & 3) * 8;
    const size_t offA = (size_t)(m0 + r) * Dd + k0 + c8;
    const size_t offB = (size_t)(n0 + r) * Dd + k0 + c8;
    const uint32_t d = st + r * 80 + c8 * 2;
    cp16(d,                 Ah + offA);
    cp16(d + MAT_BYTES,     Al + offA);
    cp16(d + 2 * MAT_BYTES, Bh + offB);
    cp16(d + 3 * MAT_BYTES, Bl + offB);
    CP_COMMIT();
}

template <int MODE>
__global__ __launch_bounds__(512)
void gemm_tc(const __nv_bfloat16* __restrict__ Ah, const __nv_bfloat16* __restrict__ Al,
             const __nv_bfloat16* __restrict__ Bh, const __nv_bfloat16* __restrict__ Bl,
             const float* __restrict__ bias, void* C0, void* C1)
{
    extern __shared__ char sm[];
    const uint32_t sbase = smem_u32(sm);

    const int tid  = threadIdx.x;
    const int wid  = tid >> 5;
    const int lane = tid & 31;
    const int m0 = blockIdx.y * 128;
    const int n0 = blockIdx.x * 128;
    const int wm = (wid & 3) * 32;
    const int wn = (wid >> 2) * 32;

    float acc[2][4][4];
#pragma unroll
    for (int mt = 0; mt < 2; mt++)
#pragma unroll
        for (int nt = 0; nt < 4; nt++)
#pragma unroll
            for (int i = 0; i < 4; i++) acc[mt][nt][i] = 0.f;

    const int a_r = lane & 15;
    const int a_k = (lane >> 4) * 8;
    const int b_r = (lane & 7) + ((lane >> 4) << 3);
    const int b_k = (lane & 8) ? 8 : 0;

    gemm_issue(sbase, tid, m0, n0, 0, Ah, Al, Bh, Bl);

    for (int c = 0; c < NCH; c++) {
        const int s = c & 1;
        if (c + 1 < NCH) {
            gemm_issue(sbase + (s ^ 1) * STAGE, tid, m0, n0, (c + 1) * GKC,
                       Ah, Al, Bh, Bl);
            CP_WAIT1();
        } else {
            CP_WAIT0();
        }
        __syncthreads();

        const uint32_t st = sbase + s * STAGE;
#pragma unroll
        for (int ks = 0; ks < 2; ks++) {
            uint32_t af[2][4], alf[2][4], bf[2][4], blf[2][4];
#pragma unroll
            for (int mt = 0; mt < 2; mt++) {
                uint32_t addr = st + (wm + mt * 16 + a_r) * 80 + (ks * 16 + a_k) * 2;
                ldsm_x4(addr, af[mt]);
                ldsm_x4(addr + MAT_BYTES, alf[mt]);
            }
#pragma unroll
            for (int nq = 0; nq < 2; nq++) {
                uint32_t addr = st + 2 * MAT_BYTES
                              + (wn + nq * 16 + b_r) * 80 + (ks * 16 + b_k) * 2;
                ldsm_x4(addr, bf[nq]);
                ldsm_x4(addr + MAT_BYTES, blf[nq]);
            }
#pragma unroll
            for (int mt = 0; mt < 2; mt++)
#pragma unroll
                for (int nt = 0; nt < 4; nt++) {
                    const uint32_t* bh = &bf[nt >> 1][(nt & 1) * 2];
                    const uint32_t* bl = &blf[nt >> 1][(nt & 1) * 2];
                    mma16816(acc[mt][nt], af[mt], bh);   // Ah*Bh
                    mma16816(acc[mt][nt], alf[mt], bh);  // Al*Bh
                    mma16816(acc[mt][nt], af[mt], bl);   // Ah*Bl
                }
        }
        __syncthreads();
    }

    // Epilogue
    const int tg = lane >> 2;
    const int tc = (lane & 3) * 2;
#pragma unroll
    for (int mt = 0; mt < 2; mt++) {
#pragma unroll
        for (int nt = 0; nt < 4; nt++) {
            const int n = n0 + wn + nt * 8 + tc;
            const float b0 = bias[n], b1 = bias[n + 1];
#pragma unroll
            for (int hf = 0; hf < 2; hf++) {
                const int m = m0 + wm + mt * 16 + tg + hf * 8;
                float v0 = acc[mt][nt][hf * 2 + 0] + b0;
                float v1 = acc[mt][nt][hf * 2 + 1] + b1;
                if (MODE == 0) {
                    *(float2*)((float*)C0 + (size_t)m * Dd + n) = make_float2(v0, v1);
                } else if (MODE == 1 || MODE == 2) {
                    if (MODE == 1) { v0 *= QSCALE; v1 *= QSCALE; }
                    const int bi = m >> 11, sr = m & 2047;
                    const int hh = n >> 6, hd = n & 63;
                    const size_t a = (((size_t)(bi * Hh + hh)) * Ss + sr) * HDd + hd;
                    __nv_bfloat16 h0 = __float2bfloat16(v0);
                    __nv_bfloat16 h1 = __float2bfloat16(v1);
                    __nv_bfloat16 l0 = __float2bfloat16(v0 - __bfloat162float(h0));
                    __nv_bfloat16 l1 = __float2bfloat16(v1 - __bfloat162float(h1));
                    uint32_t ph = (uint32_t)__bfloat16_as_ushort(h0)
                                | ((uint32_t)__bfloat16_as_ushort(h1) << 16);
                    uint32_t pl = (uint32_t)__bfloat16_as_ushort(l0)
                                | ((uint32_t)__bfloat16_as_ushort(l1) << 16);
                    *(uint32_t*)((__nv_bfloat16*)C0 + a) = ph;
                    *(uint32_t*)((__nv_bfloat16*)C1 + a) = pl;
                } else { // MODE 3: V transposed fp16 [B,H,HD,S]
                    const int bi = m >> 11, sr = m & 2047;
                    const int hh = n >> 6, hd = n & 63;
                    const size_t a = (((size_t)(bi * Hh + hh)) * HDd + hd) * Ss + sr;
                    ((__half*)C0)[a]      = __float2half(v0);
                    ((__half*)C0)[a + Ss] = __float2half(v1);
                }
            }
        }
    }
}

// ---------------------------------------------------------------------------
// Tensor-core flash attention.
// CTA: 128 q rows x full KV; 8 warps, each owns 16 q rows.
// KV tile = 128. QK^T: bf16 3-pass compensated. PV: fp16 single pass.
// Softmax in mma c-fragments (exp2 domain; scale folded into Q).
// Outputs ctx as bf16 hi/lo [B,S,D] for the compensated output GEMM.
// ---------------------------------------------------------------------------
#define QROW 144                 // bytes per Q/K smem row (64 bf16 + pad)
#define VROW 272                 // bytes per Vt smem row (128 fp16 + pad)
#define QMAT (128 * QROW)        // 18432
#define VMAT (64 * VROW)         // 17408
#define STAGEA (2 * QMAT + VMAT) // 54272
#define ATT_SMEM (2 * QMAT + 2 * STAGEA)  // 145408

__device__ __forceinline__ void attn_load_kv(
    uint32_t st, int tid, int kv0,
    const __nv_bfloat16* __restrict__ kh, const __nv_bfloat16* __restrict__ kl,
    const __half* __restrict__ vt, size_t qkbase, size_t vbase)
{
#pragma unroll
    for (int i = 0; i < 4; i++) {
        int idx = tid + i * 256;
        int r = idx >> 3, c = (idx & 7) * 8;
        cp16(st + r * QROW + c * 2,        kh + qkbase + (size_t)(kv0 + r) * HDd + c);
        cp16(st + QMAT + r * QROW + c * 2, kl + qkbase + (size_t)(kv0 + r) * HDd + c);
    }
#pragma unroll
    for (int i = 0; i < 4; i++) {
        int idx = tid + i * 256;
        int r = idx >> 4, c = (idx & 15) * 8;
        cp16(st + 2 * QMAT + r * VROW + c * 2, vt + vbase + (size_t)r * Ss + kv0 + c);
    }
}

__global__ __launch_bounds__(256)
void attn_tc(const __nv_bfloat16* __restrict__ qh, const __nv_bfloat16* __restrict__ ql,
             const __nv_bfloat16* __restrict__ kh, const __nv_bfloat16* __restrict__ kl,
             const __half* __restrict__ vt,
             __nv_bfloat16* __restrict__ ch, __nv_bfloat16* __restrict__ cl)
{
    extern __shared__ char sm[];
    const uint32_t sb = smem_u32(sm);
    const int tid = threadIdx.x;
    const int w = tid >> 5, lane = tid & 31;
    const int q0 = blockIdx.x * 128;
    const int h = blockIdx.y, b = blockIdx.z;
    const size_t qkbase = ((size_t)(b * Hh + h) * Ss) * HDd;
    const size_t vbase  = ((size_t)(b * Hh + h) * HDd) * Ss;

    // Prologue: Q (resident) + KV tile 0, single commit group
#pragma unroll
    for (int i = 0; i < 4; i++) {
        int idx = tid + i * 256;
        int r = idx >> 3, c = (idx & 7) * 8;
        cp16(sb + r * QROW + c * 2,        qh + qkbase + (size_t)(q0 + r) * HDd + c);
        cp16(sb + QMAT + r * QROW + c * 2, ql + qkbase + (size_t)(q0 + r) * HDd + c);
    }
    attn_load_kv(sb + 2 * QMAT, tid, 0, kh, kl, vt, qkbase, vbase);
    CP_COMMIT();

    const int a_r = lane & 15;
    const int a_k = (lane >> 4) * 8;
    const int b_r = (lane & 7) + ((lane >> 4) << 3);
    const int b_k = (lane & 8) ? 8 : 0;

    float o[8][4];
#pragma unroll
    for (int nt = 0; nt < 8; nt++)
#pragma unroll
        for (int i = 0; i < 4; i++) o[nt][i] = 0.f;
    float m2[2] = {-1e30f, -1e30f};
    float lsum[2] = {0.f, 0.f};
    uint32_t qa[4][2][4];

    for (int t = 0; t < Ss / 128; t++) {
        const int s = t & 1;
        const uint32_t stc = sb + 2 * QMAT + s * STAGEA;
        if (t + 1 < Ss / 128) {
            attn_load_kv(sb + 2 * QMAT + (s ^ 1) * STAGEA, tid, (t + 1) * 128,
                         kh, kl, vt, qkbase, vbase);
            CP_COMMIT();
            CP_WAIT1();
        } else {
            CP_WAIT0();
        }
        __syncthreads();

        if (t == 0) {
#pragma unroll
            for (int kc = 0; kc < 4; kc++) {
                uint32_t ad = sb + (w * 16 + a_r) * QROW + (kc * 16 + a_k) * 2;
                ldsm_x4(ad, qa[kc][0]);
                ldsm_x4(ad + QMAT, qa[kc][1]);
            }
        }

        // ---- scores S = Q K^T (3-pass compensated bf16) ----
        float sc[16][4];
#pragma unroll
        for (int nt = 0; nt < 16; nt++)
#pragma unroll
            for (int i = 0; i < 4; i++) sc[nt][i] = 0.f;

#pragma unroll
        for (int kc = 0; kc < 4; kc++) {
#pragma unroll
            for (int g = 0; g < 8; g++) {
                uint32_t bh[4], bl[4];
                uint32_t ad = stc + (g * 16 + b_r) * QROW + (kc * 16 + b_k) * 2;
                ldsm_x4(ad, bh);
                ldsm_x4(ad + QMAT, bl);
                mma16816(sc[2 * g],     qa[kc][0], bh);
                mma16816(sc[2 * g],     qa[kc][1], bh);
                mma16816(sc[2 * g],     qa[kc][0], bl);
                mma16816(sc[2 * g + 1], qa[kc][0], bh + 2);
                mma16816(sc[2 * g + 1], qa[kc][1], bh + 2);
                mma16816(sc[2 * g + 1], qa[kc][0], bl + 2);
            }
        }

        // ---- online softmax (exp2 domain; rows split over 4-lane groups) ----
#pragma unroll
        for (int rh = 0; rh < 2; rh++) {
            const int c0 = rh * 2;
            float mx = -1e30f;
#pragma unroll
            for (int nt = 0; nt < 16; nt++)
                mx = fmaxf(mx, fmaxf(sc[nt][c0], sc[nt][c0 + 1]));
            mx = fmaxf(mx, __shfl_xor_sync(0xffffffffu, mx, 1));
            mx = fmaxf(mx, __shfl_xor_sync(0xffffffffu, mx, 2));
            float mn = fmaxf(m2[rh], mx);
            float al = ex2(m2[rh] - mn);
            m2[rh] = mn;
            float rs = 0.f;
#pragma unroll
            for (int nt = 0; nt < 16; nt++) {
                sc[nt][c0]     = ex2(sc[nt][c0] - mn);
                sc[nt][c0 + 1] = ex2(sc[nt][c0 + 1] - mn);
                rs += sc[nt][c0] + sc[nt][c0 + 1];
            }
            rs += __shfl_xor_sync(0xffffffffu, rs, 1);
            rs += __shfl_xor_sync(0xffffffffu, rs, 2);
            lsum[rh] = lsum[rh] * al + rs;
#pragma unroll
            for (int nt = 0; nt < 8; nt++) {
                o[nt][c0]     *= al;
                o[nt][c0 + 1] *= al;
            }
        }

        // ---- P (c-frag) -> fp16 A-frags, register-only ----
        uint32_t pa[8][4];
#pragma unroll
        for (int kc = 0; kc < 8; kc++) {
            pa[kc][0] = pack_h2(sc[2 * kc][0],     sc[2 * kc][1]);
            pa[kc][1] = pack_h2(sc[2 * kc][2],     sc[2 * kc][3]);
            pa[kc][2] = pack_h2(sc[2 * kc + 1][0], sc[2 * kc + 1][1]);
            pa[kc][3] = pack_h2(sc[2 * kc + 1][2], sc[2 * kc + 1][3]);
        }

        // ---- O += P V (fp16) ----
        const uint32_t vs = stc + 2 * QMAT;
#pragma unroll
        for (int g = 0; g < 4; g++) {
#pragma unroll
            for (int kc = 0; kc < 8; kc++) {
                uint32_t vb[4];
                ldsm_x4(vs + (g * 16 + b_r) * VROW + (kc * 16 + b_k) * 2, vb);
                mma16816h(o[2 * g],     pa[kc], vb);
                mma16816h(o[2 * g + 1], pa[kc], vb + 2);
            }
        }
        __syncthreads();
    }

    // ---- epilogue: ctx = O/l as bf16 hi/lo, [B,S,D] layout ----
    const int tg = lane >> 2;
    const int tc2 = (lane & 3) * 2;
#pragma unroll
    for (int rh = 0; rh < 2; rh++) {
        float inv = 1.f / lsum[rh];
        int srow = q0 + w * 16 + tg + rh * 8;
#pragma unroll
        for (int nt = 0; nt < 8; nt++) {
            float v0 = o[nt][rh * 2] * inv;
            float v1 = o[nt][rh * 2 + 1] * inv;
            __nv_bfloat16 h0 = __float2bfloat16(v0);
            __nv_bfloat16 h1 = __float2bfloat16(v1);
            __nv_bfloat16 l0 = __float2bfloat16(v0 - __bfloat162float(h0));
            __nv_bfloat16 l1 = __float2bfloat16(v1 - __bfloat162float(h1));
            uint32_t ph = (uint32_t)__bfloat16_as_ushort(h0)
                        | ((uint32_t)__bfloat16_as_ushort(h1) << 16);
            uint32_t pl = (uint32_t)__bfloat16_as_ushort(l0)
                        | ((uint32_t)__bfloat16_as_ushort(l1) << 16);
            size_t a = ((size_t)b * Ss + srow) * Dd + h * HDd + nt * 8 + tc2;
            *(uint32_t*)(ch + a) = ph;
            *(uint32_t*)(cl + a) = pl;
        }
    }
}

// ---------------------------------------------------------------------------
extern "C" void kernel_launch(void* const* d_in, const int* in_sizes, int n_in,
                              void* d_out, int out_size)
{
    const float* x  = (const float*)d_in[0];
    const float* Wq = (const float*)d_in[1];
    const float* bq = (const float*)d_in[2];
    const float* Wk = (const float*)d_in[3];
    const float* bk = (const float*)d_in[4];
    const float* Wv = (const float*)d_in[5];
    const float* bv = (const float*)d_in[6];
    const float* Wo = (const float*)d_in[7];
    const float* bo = (const float*)d_in[8];
    float* out = (float*)d_out;

    __nv_bfloat16 *xh, *xl, *wh, *wl, *qhp, *qlp, *khp, *klp, *chp, *clp;
    __half *vtp;
    cudaGetSymbolAddress((void**)&xh,  g_xh);
    cudaGetSymbolAddress((void**)&xl,  g_xl);
    cudaGetSymbolAddress((void**)&wh,  g_wh);
    cudaGetSymbolAddress((void**)&wl,  g_wl);
    cudaGetSymbolAddress((void**)&qhp, g_qh);
    cudaGetSymbolAddress((void**)&qlp, g_ql);
    cudaGetSymbolAddress((void**)&khp, g_kh);
    cudaGetSymbolAddress((void**)&klp, g_kl);
    cudaGetSymbolAddress((void**)&vtp, g_vt);
    cudaGetSymbolAddress((void**)&chp, g_ch);
    cudaGetSymbolAddress((void**)&clp, g_cl);

    cudaFuncSetAttribute((const void*)gemm_tc<0>,
                         cudaFuncAttributeMaxDynamicSharedMemorySize, GSMEM);
    cudaFuncSetAttribute((const void*)gemm_tc<1>,
                         cudaFuncAttributeMaxDynamicSharedMemorySize, GSMEM);
    cudaFuncSetAttribute((const void*)gemm_tc<2>,
                         cudaFuncAttributeMaxDynamicSharedMemorySize, GSMEM);
    cudaFuncSetAttribute((const void*)gemm_tc<3>,
                         cudaFuncAttributeMaxDynamicSharedMemorySize, GSMEM);
    cudaFuncSetAttribute(attn_tc,
                         cudaFuncAttributeMaxDynamicSharedMemorySize, ATT_SMEM);

    // Split fp32 -> bf16 hi/lo
    const int nx4 = (Mm * Dd) / 4;
    const int nw4 = (Dd * Dd) / 4;
    split_kernel<<<nx4 / 256, 256>>>((const float4*)x, (uint2*)xh, (uint2*)xl, nx4);
    const float* Ws[4] = {Wq, Wk, Wv, Wo};
    for (int i = 0; i < 4; i++)
        split_kernel<<<nw4 / 256, 256>>>((const float4*)Ws[i],
                                         (uint2*)(wh + (size_t)i * Dd * Dd),
                                         (uint2*)(wl + (size_t)i * Dd * Dd), nw4);

    dim3 gg(Dd / 128, Mm / 128);   // (8, 64)
    gemm_tc<1><<<gg, 512, GSMEM>>>(xh, xl, wh, wl, bq, qhp, qlp);
    gemm_tc<2><<<gg, 512, GSMEM>>>(xh, xl, wh + (size_t)Dd * Dd, wl + (size_t)Dd * Dd,
                                   bk, khp, klp);
    gemm_tc<3><<<gg, 512, GSMEM>>>(xh, xl, wh + 2 * (size_t)Dd * Dd, wl + 2 * (size_t)Dd * Dd,
                                   bv, vtp, nullptr);

    dim3 ga(Ss / 128, Hh, Bb);     // (16, 16, 4)
    attn_tc<<<ga, 256, ATT_SMEM>>>(qhp, qlp, khp, klp, vtp, chp, clp);

    gemm_tc<0><<<gg, 512, GSMEM>>>(chp, clp, wh + 3 * (size_t)Dd * Dd, wl + 3 * (size_t)Dd * Dd,
                                   bo, out, nullptr);
}

// round 6
// speedup vs baseline: 5.4639x; 1.3569x over previous
#include <cuda_runtime.h>
#include <cuda_bf16.h>
#include <cuda_fp16.h>
#include <math.h>
#include <stdint.h>

#define Bb  4
#define Ss  2048
#define Dd  1024
#define Hh  16
#define HDd 64
#define Mm  (Bb*Ss)   // 8192

// ---------------------------------------------------------------------------
// Scratch (device globals: allocation-free per harness rules)
// ---------------------------------------------------------------------------
__device__ __half g_xh[(size_t)Mm * Dd];
__device__ __half g_xl[(size_t)Mm * Dd];
__device__ __half g_w [(size_t)4 * Dd * Dd];
__device__ __half g_qh[(size_t)Mm * Dd];
__device__ __half g_ql[(size_t)Mm * Dd];
__device__ __half g_k [(size_t)Mm * Dd];
__device__ __half g_vt[(size_t)Mm * Dd];
__device__ __half g_ch[(size_t)Mm * Dd];
__device__ __half g_cl[(size_t)Mm * Dd];

// 0.125 * log2(e)  (folded into Q so softmax runs in exp2 domain)
#define QSCALE 0.18033688011112042f

// ---------------------------------------------------------------------------
// Helpers
// ---------------------------------------------------------------------------
__device__ __forceinline__ uint32_t smem_u32(const void* p) {
    uint32_t a;
    asm("{ .reg .u64 t; cvta.to.shared.u64 t, %1; cvt.u32.u64 %0, t; }"
        : "=r"(a) : "l"(p));
    return a;
}

__device__ __forceinline__ float ex2(float x) {
    float y;
    asm("ex2.approx.ftz.f32 %0, %1;" : "=f"(y) : "f"(x));
    return y;
}

__device__ __forceinline__ void ldsm_x4(uint32_t addr, uint32_t* r) {
    asm volatile("ldmatrix.sync.aligned.m8n8.x4.shared.b16 {%0,%1,%2,%3}, [%4];"
        : "=r"(r[0]), "=r"(r[1]), "=r"(r[2]), "=r"(r[3]) : "r"(addr));
}

__device__ __forceinline__ void mma16816h(float* c, const uint32_t* a, const uint32_t* b) {
    asm volatile(
        "mma.sync.aligned.m16n8k16.row.col.f32.f16.f16.f32 "
        "{%0,%1,%2,%3}, {%4,%5,%6,%7}, {%8,%9}, {%0,%1,%2,%3};"
        : "+f"(c[0]), "+f"(c[1]), "+f"(c[2]), "+f"(c[3])
        : "r"(a[0]), "r"(a[1]), "r"(a[2]), "r"(a[3]), "r"(b[0]), "r"(b[1]));
}

__device__ __forceinline__ uint32_t pack_h2(float a, float b) {
    __half2 h = __floats2half2_rn(a, b);
    return *(uint32_t*)&h;
}

// split one float into fp16 hi + fp16 lo (residual)
__device__ __forceinline__ void split1(float v, __half& h, __half& l) {
    h = __float2half_rn(v);
    l = __float2half_rn(v - __half2float(h));
}

__device__ __forceinline__ void cp16(uint32_t dst, const void* src) {
    asm volatile("cp.async.cg.shared.global [%0], [%1], 16;" :: "r"(dst), "l"(src));
}
#define CP_COMMIT() asm volatile("cp.async.commit_group;" ::: "memory")
#define CP_WAIT1()  asm volatile("cp.async.wait_group 1;" ::: "memory")
#define CP_WAIT0()  asm volatile("cp.async.wait_group 0;" ::: "memory")

// ---------------------------------------------------------------------------
// fp32 -> fp16 hi/lo split  and  fp32 -> fp16 cast (bandwidth-bound)
// ---------------------------------------------------------------------------
__global__ __launch_bounds__(256)
void split_kernel(const float4* __restrict__ in, uint2* __restrict__ hi,
                  uint2* __restrict__ lo, int n4)
{
    int i = blockIdx.x * blockDim.x + threadIdx.x;
    if (i < n4) {
        float4 v = in[i];
        __half h0, h1, h2, h3, l0, l1, l2, l3;
        split1(v.x, h0, l0); split1(v.y, h1, l1);
        split1(v.z, h2, l2); split1(v.w, h3, l3);
        __half2 ha = __halves2half2(h0, h1), hb = __halves2half2(h2, h3);
        __half2 la = __halves2half2(l0, l1), lb = __halves2half2(l2, l3);
        hi[i] = make_uint2(*(uint32_t*)&ha, *(uint32_t*)&hb);
        lo[i] = make_uint2(*(uint32_t*)&la, *(uint32_t*)&lb);
    }
}

__global__ __launch_bounds__(256)
void cast_kernel(const float4* __restrict__ in, uint2* __restrict__ out, int n4)
{
    int i = blockIdx.x * blockDim.x + threadIdx.x;
    if (i < n4) {
        float4 v = in[i];
        __half2 a = __floats2half2_rn(v.x, v.y);
        __half2 b = __floats2half2_rn(v.z, v.w);
        out[i] = make_uint2(*(uint32_t*)&a, *(uint32_t*)&b);
    }
}

// ---------------------------------------------------------------------------
// HMMA GEMM (2-pass fp16): C[M,N] = A[M,K] @ W[N,K]^T + bias[N]
//   A given as hi/lo fp16 (exact to 2^-22), W plain fp16 (err 2^-11).
// 128x128 CTA tile, 512 threads, KC=32, 2-stage cp.async, 3 smem mats/stage.
// MODE 0: fp32 [M,N] out.
// MODE 1: Q out — scaled by QSCALE, fp16 hi/lo, remap to [B,H,S,HD].
// MODE 2: K out — fp16, remap to [B,H,S,HD].
// MODE 3: V out — fp16, remap TRANSPOSED to [B,H,HD,S].
// ---------------------------------------------------------------------------
#define GKC 32
#define NCH (Dd / GKC)          // 32
#define MAT_BYTES (128 * 80)    // 10240
#define STAGE (3 * MAT_BYTES)   // 30720
#define GSMEM (2 * STAGE)       // 61440

__device__ __forceinline__ void gemm_issue(
    uint32_t st, int tid, int m0, int n0, int k0,
    const __half* __restrict__ Ah, const __half* __restrict__ Al,
    const __half* __restrict__ Bh)
{
    const int r  = tid >> 2;
    const int c8 = (tid & 3) * 8;
    const size_t offA = (size_t)(m0 + r) * Dd + k0 + c8;
    const size_t offB = (size_t)(n0 + r) * Dd + k0 + c8;
    const uint32_t d = st + r * 80 + c8 * 2;
    cp16(d,                 Ah + offA);
    cp16(d + MAT_BYTES,     Al + offA);
    cp16(d + 2 * MAT_BYTES, Bh + offB);
    CP_COMMIT();
}

template <int MODE>
__global__ __launch_bounds__(512)
void gemm_tc(const __half* __restrict__ Ah, const __half* __restrict__ Al,
             const __half* __restrict__ Bh,
             const float* __restrict__ bias, void* C0, void* C1)
{
    extern __shared__ char sm[];
    const uint32_t sbase = smem_u32(sm);

    const int tid  = threadIdx.x;
    const int wid  = tid >> 5;
    const int lane = tid & 31;
    const int m0 = blockIdx.y * 128;
    const int n0 = blockIdx.x * 128;
    const int wm = (wid & 3) * 32;
    const int wn = (wid >> 2) * 32;

    float acc[2][4][4];
#pragma unroll
    for (int mt = 0; mt < 2; mt++)
#pragma unroll
        for (int nt = 0; nt < 4; nt++)
#pragma unroll
            for (int i = 0; i < 4; i++) acc[mt][nt][i] = 0.f;

    const int a_r = lane & 15;
    const int a_k = (lane >> 4) * 8;
    const int b_r = (lane & 7) + ((lane >> 4) << 3);
    const int b_k = (lane & 8) ? 8 : 0;

    gemm_issue(sbase, tid, m0, n0, 0, Ah, Al, Bh);

    for (int c = 0; c < NCH; c++) {
        const int s = c & 1;
        if (c + 1 < NCH) {
            gemm_issue(sbase + (s ^ 1) * STAGE, tid, m0, n0, (c + 1) * GKC,
                       Ah, Al, Bh);
            CP_WAIT1();
        } else {
            CP_WAIT0();
        }
        __syncthreads();

        const uint32_t st = sbase + s * STAGE;
#pragma unroll
        for (int ks = 0; ks < 2; ks++) {
            uint32_t af[2][4], alf[2][4], bf[2][4];
#pragma unroll
            for (int mt = 0; mt < 2; mt++) {
                uint32_t addr = st + (wm + mt * 16 + a_r) * 80 + (ks * 16 + a_k) * 2;
                ldsm_x4(addr, af[mt]);
                ldsm_x4(addr + MAT_BYTES, alf[mt]);
            }
#pragma unroll
            for (int nq = 0; nq < 2; nq++) {
                uint32_t addr = st + 2 * MAT_BYTES
                              + (wn + nq * 16 + b_r) * 80 + (ks * 16 + b_k) * 2;
                ldsm_x4(addr, bf[nq]);
            }
#pragma unroll
            for (int mt = 0; mt < 2; mt++)
#pragma unroll
                for (int nt = 0; nt < 4; nt++) {
                    const uint32_t* bh = &bf[nt >> 1][(nt & 1) * 2];
                    mma16816h(acc[mt][nt], af[mt], bh);   // Ah*B
                    mma16816h(acc[mt][nt], alf[mt], bh);  // Al*B
                }
        }
        __syncthreads();
    }

    // Epilogue
    const int tg = lane >> 2;
    const int tc = (lane & 3) * 2;
#pragma unroll
    for (int mt = 0; mt < 2; mt++) {
#pragma unroll
        for (int nt = 0; nt < 4; nt++) {
            const int n = n0 + wn + nt * 8 + tc;
            const float b0 = bias[n], b1 = bias[n + 1];
#pragma unroll
            for (int hf = 0; hf < 2; hf++) {
                const int m = m0 + wm + mt * 16 + tg + hf * 8;
                float v0 = acc[mt][nt][hf * 2 + 0] + b0;
                float v1 = acc[mt][nt][hf * 2 + 1] + b1;
                if (MODE == 0) {
                    *(float2*)((float*)C0 + (size_t)m * Dd + n) = make_float2(v0, v1);
                } else if (MODE == 1) {
                    v0 *= QSCALE; v1 *= QSCALE;
                    const int bi = m >> 11, sr = m & 2047;
                    const int hh = n >> 6, hd = n & 63;
                    const size_t a = (((size_t)(bi * Hh + hh)) * Ss + sr) * HDd + hd;
                    __half h0, h1, l0, l1;
                    split1(v0, h0, l0); split1(v1, h1, l1);
                    __half2 ph = __halves2half2(h0, h1);
                    __half2 pl = __halves2half2(l0, l1);
                    *(uint32_t*)((__half*)C0 + a) = *(uint32_t*)&ph;
                    *(uint32_t*)((__half*)C1 + a) = *(uint32_t*)&pl;
                } else if (MODE == 2) {
                    const int bi = m >> 11, sr = m & 2047;
                    const int hh = n >> 6, hd = n & 63;
                    const size_t a = (((size_t)(bi * Hh + hh)) * Ss + sr) * HDd + hd;
                    __half2 ph = __floats2half2_rn(v0, v1);
                    *(uint32_t*)((__half*)C0 + a) = *(uint32_t*)&ph;
                } else { // MODE 3: V transposed fp16 [B,H,HD,S]
                    const int bi = m >> 11, sr = m & 2047;
                    const int hh = n >> 6, hd = n & 63;
                    const size_t a = (((size_t)(bi * Hh + hh)) * HDd + hd) * Ss + sr;
                    ((__half*)C0)[a]      = __float2half(v0);
                    ((__half*)C0)[a + Ss] = __float2half(v1);
                }
            }
        }
    }
}

// ---------------------------------------------------------------------------
// Tensor-core flash attention.
// CTA: 128 q rows x full KV; 8 warps, each owns 16 q rows.
// KV tile = 128. QK^T: 2-pass fp16 (Q hi/lo, K plain). PV: fp16 single pass.
// Softmax in mma c-fragments (exp2 domain; scale folded into Q).
// Outputs ctx as fp16 hi/lo [B,S,D] for the 2-pass output GEMM.
// ---------------------------------------------------------------------------
#define QROW 144                 // bytes per Q/K smem row (64 fp16 + pad)
#define VROW 272                 // bytes per Vt smem row (128 fp16 + pad)
#define QMAT (128 * QROW)        // 18432
#define KMAT (128 * QROW)        // 18432
#define VMAT (64 * VROW)         // 17408
#define STAGEA (KMAT + VMAT)     // 35840
#define ATT_SMEM (2 * QMAT + 2 * STAGEA)  // 108544

__device__ __forceinline__ void attn_load_kv(
    uint32_t st, int tid, int kv0,
    const __half* __restrict__ kp, const __half* __restrict__ vt,
    size_t qkbase, size_t vbase)
{
#pragma unroll
    for (int i = 0; i < 4; i++) {
        int idx = tid + i * 256;
        int r = idx >> 3, c = (idx & 7) * 8;
        cp16(st + r * QROW + c * 2, kp + qkbase + (size_t)(kv0 + r) * HDd + c);
    }
#pragma unroll
    for (int i = 0; i < 4; i++) {
        int idx = tid + i * 256;
        int r = idx >> 4, c = (idx & 15) * 8;
        cp16(st + KMAT + r * VROW + c * 2, vt + vbase + (size_t)r * Ss + kv0 + c);
    }
}

__global__ __launch_bounds__(256)
void attn_tc(const __half* __restrict__ qh, const __half* __restrict__ ql,
             const __half* __restrict__ kp, const __half* __restrict__ vt,
             __half* __restrict__ ch, __half* __restrict__ cl)
{
    extern __shared__ char sm[];
    const uint32_t sb = smem_u32(sm);
    const int tid = threadIdx.x;
    const int w = tid >> 5, lane = tid & 31;
    const int q0 = blockIdx.x * 128;
    const int h = blockIdx.y, b = blockIdx.z;
    const size_t qkbase = ((size_t)(b * Hh + h) * Ss) * HDd;
    const size_t vbase  = ((size_t)(b * Hh + h) * HDd) * Ss;

    // Prologue: Q hi/lo (resident) + KV tile 0, single commit group
#pragma unroll
    for (int i = 0; i < 4; i++) {
        int idx = tid + i * 256;
        int r = idx >> 3, c = (idx & 7) * 8;
        cp16(sb + r * QROW + c * 2,        qh + qkbase + (size_t)(q0 + r) * HDd + c);
        cp16(sb + QMAT + r * QROW + c * 2, ql + qkbase + (size_t)(q0 + r) * HDd + c);
    }
    attn_load_kv(sb + 2 * QMAT, tid, 0, kp, vt, qkbase, vbase);
    CP_COMMIT();

    const int a_r = lane & 15;
    const int a_k = (lane >> 4) * 8;
    const int b_r = (lane & 7) + ((lane >> 4) << 3);
    const int b_k = (lane & 8) ? 8 : 0;

    float o[8][4];
#pragma unroll
    for (int nt = 0; nt < 8; nt++)
#pragma unroll
        for (int i = 0; i < 4; i++) o[nt][i] = 0.f;
    float m2[2] = {-1e30f, -1e30f};
    float lsum[2] = {0.f, 0.f};
    uint32_t qa[4][2][4];

    for (int t = 0; t < Ss / 128; t++) {
        const int s = t & 1;
        const uint32_t stc = sb + 2 * QMAT + s * STAGEA;
        if (t + 1 < Ss / 128) {
            attn_load_kv(sb + 2 * QMAT + (s ^ 1) * STAGEA, tid, (t + 1) * 128,
                         kp, vt, qkbase, vbase);
            CP_COMMIT();
            CP_WAIT1();
        } else {
            CP_WAIT0();
        }
        __syncthreads();

        if (t == 0) {
#pragma unroll
            for (int kc = 0; kc < 4; kc++) {
                uint32_t ad = sb + (w * 16 + a_r) * QROW + (kc * 16 + a_k) * 2;
                ldsm_x4(ad, qa[kc][0]);
                ldsm_x4(ad + QMAT, qa[kc][1]);
            }
        }

        // ---- scores S = Q K^T (2-pass fp16: Qh*K + Ql*K) ----
        float sc[16][4];
#pragma unroll
        for (int nt = 0; nt < 16; nt++)
#pragma unroll
            for (int i = 0; i < 4; i++) sc[nt][i] = 0.f;

#pragma unroll
        for (int kc = 0; kc < 4; kc++) {
#pragma unroll
            for (int g = 0; g < 8; g++) {
                uint32_t bh[4];
                uint32_t ad = stc + (g * 16 + b_r) * QROW + (kc * 16 + b_k) * 2;
                ldsm_x4(ad, bh);
                mma16816h(sc[2 * g],     qa[kc][0], bh);
                mma16816h(sc[2 * g],     qa[kc][1], bh);
                mma16816h(sc[2 * g + 1], qa[kc][0], bh + 2);
                mma16816h(sc[2 * g + 1], qa[kc][1], bh + 2);
            }
        }

        // ---- online softmax (exp2 domain; rows split over 4-lane groups) ----
#pragma unroll
        for (int rh = 0; rh < 2; rh++) {
            const int c0 = rh * 2;
            float mx = -1e30f;
#pragma unroll
            for (int nt = 0; nt < 16; nt++)
                mx = fmaxf(mx, fmaxf(sc[nt][c0], sc[nt][c0 + 1]));
            mx = fmaxf(mx, __shfl_xor_sync(0xffffffffu, mx, 1));
            mx = fmaxf(mx, __shfl_xor_sync(0xffffffffu, mx, 2));
            float mn = fmaxf(m2[rh], mx);
            float al = ex2(m2[rh] - mn);
            m2[rh] = mn;
            float rs = 0.f;
#pragma unroll
            for (int nt = 0; nt < 16; nt++) {
                sc[nt][c0]     = ex2(sc[nt][c0] - mn);
                sc[nt][c0 + 1] = ex2(sc[nt][c0 + 1] - mn);
                rs += sc[nt][c0] + sc[nt][c0 + 1];
            }
            rs += __shfl_xor_sync(0xffffffffu, rs, 1);
            rs += __shfl_xor_sync(0xffffffffu, rs, 2);
            lsum[rh] = lsum[rh] * al + rs;
#pragma unroll
            for (int nt = 0; nt < 8; nt++) {
                o[nt][c0]     *= al;
                o[nt][c0 + 1] *= al;
            }
        }

        // ---- P (c-frag) -> fp16 A-frags, register-only ----
        uint32_t pa[8][4];
#pragma unroll
        for (int kc = 0; kc < 8; kc++) {
            pa[kc][0] = pack_h2(sc[2 * kc][0],     sc[2 * kc][1]);
            pa[kc][1] = pack_h2(sc[2 * kc][2],     sc[2 * kc][3]);
            pa[kc][2] = pack_h2(sc[2 * kc + 1][0], sc[2 * kc + 1][1]);
            pa[kc][3] = pack_h2(sc[2 * kc + 1][2], sc[2 * kc + 1][3]);
        }

        // ---- O += P V (fp16) ----
        const uint32_t vs = stc + KMAT;
#pragma unroll
        for (int g = 0; g < 4; g++) {
#pragma unroll
            for (int kc = 0; kc < 8; kc++) {
                uint32_t vb[4];
                ldsm_x4(vs + (g * 16 + b_r) * VROW + (kc * 16 + b_k) * 2, vb);
                mma16816h(o[2 * g],     pa[kc], vb);
                mma16816h(o[2 * g + 1], pa[kc], vb + 2);
            }
        }
        __syncthreads();
    }

    // ---- epilogue: ctx = O/l as fp16 hi/lo, [B,S,D] layout ----
    const int tg = lane >> 2;
    const int tc2 = (lane & 3) * 2;
#pragma unroll
    for (int rh = 0; rh < 2; rh++) {
        float inv = 1.f / lsum[rh];
        int srow = q0 + w * 16 + tg + rh * 8;
#pragma unroll
        for (int nt = 0; nt < 8; nt++) {
            float v0 = o[nt][rh * 2] * inv;
            float v1 = o[nt][rh * 2 + 1] * inv;
            __half h0, h1, l0, l1;
            split1(v0, h0, l0); split1(v1, h1, l1);
            __half2 ph = __halves2half2(h0, h1);
            __half2 pl = __halves2half2(l0, l1);
            size_t a = ((size_t)b * Ss + srow) * Dd + h * HDd + nt * 8 + tc2;
            *(uint32_t*)(ch + a) = *(uint32_t*)&ph;
            *(uint32_t*)(cl + a) = *(uint32_t*)&pl;
        }
    }
}

// ---------------------------------------------------------------------------
extern "C" void kernel_launch(void* const* d_in, const int* in_sizes, int n_in,
                              void* d_out, int out_size)
{
    const float* x  = (const float*)d_in[0];
    const float* Wq = (const float*)d_in[1];
    const float* bq = (const float*)d_in[2];
    const float* Wk = (const float*)d_in[3];
    const float* bk = (const float*)d_in[4];
    const float* Wv = (const float*)d_in[5];
    const float* bv = (const float*)d_in[6];
    const float* Wo = (const float*)d_in[7];
    const float* bo = (const float*)d_in[8];
    float* out = (float*)d_out;

    __half *xh, *xl, *wp, *qhp, *qlp, *kpp, *vtp, *chp, *clp;
    cudaGetSymbolAddress((void**)&xh,  g_xh);
    cudaGetSymbolAddress((void**)&xl,  g_xl);
    cudaGetSymbolAddress((void**)&wp,  g_w);
    cudaGetSymbolAddress((void**)&qhp, g_qh);
    cudaGetSymbolAddress((void**)&qlp, g_ql);
    cudaGetSymbolAddress((void**)&kpp, g_k);
    cudaGetSymbolAddress((void**)&vtp, g_vt);
    cudaGetSymbolAddress((void**)&chp, g_ch);
    cudaGetSymbolAddress((void**)&clp, g_cl);

    cudaFuncSetAttribute((const void*)gemm_tc<0>,
                         cudaFuncAttributeMaxDynamicSharedMemorySize, GSMEM);
    cudaFuncSetAttribute((const void*)gemm_tc<1>,
                         cudaFuncAttributeMaxDynamicSharedMemorySize, GSMEM);
    cudaFuncSetAttribute((const void*)gemm_tc<2>,
                         cudaFuncAttributeMaxDynamicSharedMemorySize, GSMEM);
    cudaFuncSetAttribute((const void*)gemm_tc<3>,
                         cudaFuncAttributeMaxDynamicSharedMemorySize, GSMEM);
    cudaFuncSetAttribute(attn_tc,
                         cudaFuncAttributeMaxDynamicSharedMemorySize, ATT_SMEM);

    // x -> fp16 hi/lo ; W -> fp16
    const int nx4 = (Mm * Dd) / 4;
    const int nw4 = (Dd * Dd) / 4;
    split_kernel<<<nx4 / 256, 256>>>((const float4*)x, (uint2*)xh, (uint2*)xl, nx4);
    const float* Ws[4] = {Wq, Wk, Wv, Wo};
    for (int i = 0; i < 4; i++)
        cast_kernel<<<nw4 / 256, 256>>>((const float4*)Ws[i],
                                        (uint2*)(wp + (size_t)i * Dd * Dd), nw4);

    dim3 gg(Dd / 128, Mm / 128);   // (8, 64)
    gemm_tc<1><<<gg, 512, GSMEM>>>(xh, xl, wp,                         bq, qhp, qlp);
    gemm_tc<2><<<gg, 512, GSMEM>>>(xh, xl, wp + (size_t)Dd * Dd,       bk, kpp, nullptr);
    gemm_tc<3><<<gg, 512, GSMEM>>>(xh, xl, wp + 2 * (size_t)Dd * Dd,   bv, vtp, nullptr);

    dim3 ga(Ss / 128, Hh, Bb);     // (16, 16, 4)
    attn_tc<<<ga, 256, ATT_SMEM>>>(qhp, qlp, kpp, vtp, chp, clp);

    gemm_tc<0><<<gg, 512, GSMEM>>>(chp, clp, wp + 3 * (size_t)Dd * Dd, bo, out, nullptr);
}